// round 1
// baseline (speedup 1.0000x reference)
#include <cuda_runtime.h>
#include <cstddef>

#define BSZ 32
#define SEQ 512
#define IND 512
#define HID 1024
#define G4  4096

// 256 MiB scratch for xU = x @ [Uf|Ui|Uo|Ug] + b   (layout [BSZ*SEQ][4096])
__device__ float g_xU[(size_t)BSZ * SEQ * G4];
__device__ unsigned long long g_count;

// ------------------------------------------------------------------
// Phase A: xU[m][n] = sum_k X[m][k] * Ucat[k][n] + bcat[n]
// 128x128 block tile, BK=8, 256 threads, 8x8 register tile
// ------------------------------------------------------------------
__global__ __launch_bounds__(256) void gemm_xU_kernel(
    const float* __restrict__ X,
    const float* __restrict__ Uf, const float* __restrict__ Ui,
    const float* __restrict__ Uo, const float* __restrict__ Ug,
    const float* __restrict__ bf, const float* __restrict__ bi,
    const float* __restrict__ bo, const float* __restrict__ bg)
{
    __shared__ float As[8][128];
    __shared__ float Bs[8][128];

    const int tid = threadIdx.x;
    const int n0  = blockIdx.x * 128;     // [0, 4096)
    const int m0  = blockIdx.y * 128;     // [0, 16384)
    const int gate = n0 >> 10;            // 128 | 1024 -> block within one gate
    const float* U  = (gate == 0) ? Uf : (gate == 1) ? Ui : (gate == 2) ? Uo : Ug;
    const float* bv = (gate == 0) ? bf : (gate == 1) ? bi : (gate == 2) ? bo : bg;
    const int cg0 = n0 & 1023;

    const int ty = tid >> 4, tx = tid & 15;
    const int mf = ty * 8,  nf = tx * 8;

    float acc[8][8];
    #pragma unroll
    for (int i = 0; i < 8; ++i)
        #pragma unroll
        for (int j = 0; j < 8; ++j) acc[i][j] = 0.f;

    const int lrow = tid >> 1;            // 0..127
    const int lkq  = (tid & 1) * 4;       // 0 or 4
    const int lkr  = tid >> 5;            // 0..7
    const int lnn  = (tid & 31) * 4;      // 0..124

    for (int k0 = 0; k0 < IND; k0 += 8) {
        float4 xv = *(const float4*)(X + (size_t)(m0 + lrow) * IND + k0 + lkq);
        float4 uv = *(const float4*)(U + (size_t)(k0 + lkr) * HID + cg0 + lnn);
        __syncthreads();
        As[lkq + 0][lrow] = xv.x;
        As[lkq + 1][lrow] = xv.y;
        As[lkq + 2][lrow] = xv.z;
        As[lkq + 3][lrow] = xv.w;
        *(float4*)&Bs[lkr][lnn] = uv;
        __syncthreads();
        #pragma unroll
        for (int kk = 0; kk < 8; ++kk) {
            float4 a0 = *(const float4*)&As[kk][mf];
            float4 a1 = *(const float4*)&As[kk][mf + 4];
            float4 c0 = *(const float4*)&Bs[kk][nf];
            float4 c1 = *(const float4*)&Bs[kk][nf + 4];
            float av[8] = {a0.x, a0.y, a0.z, a0.w, a1.x, a1.y, a1.z, a1.w};
            float bw[8] = {c0.x, c0.y, c0.z, c0.w, c1.x, c1.y, c1.z, c1.w};
            #pragma unroll
            for (int i = 0; i < 8; ++i)
                #pragma unroll
                for (int j = 0; j < 8; ++j)
                    acc[i][j] = fmaf(av[i], bw[j], acc[i][j]);
        }
    }

    #pragma unroll
    for (int i = 0; i < 8; ++i) {
        float* dst = g_xU + (size_t)(m0 + mf + i) * G4 + n0 + nf;
        #pragma unroll
        for (int j = 0; j < 8; ++j)
            dst[j] = acc[i][j] + bv[cg0 + nf + j];
    }
}

// ------------------------------------------------------------------
// Phase B: persistent LSTM recurrence.
// 128 blocks x 256 threads; block owns 8 hidden units (32 V columns:
// col c = gate*8 + u). V slice (1024x32 fp32 = 128KB) persists in smem.
// Per step: gates[32b][32c] = h_{t-1}[32][1024] @ Vslice, + xU, pointwise,
// write h_t into hidden_seq (also the h state buffer), grid barrier.
// 256 threads = 4 K-groups of 64; each thread: 4 batches x 4 cols.
// ------------------------------------------------------------------
#define SMEM_FLOATS 46336
#define SMEM_BYTES  (SMEM_FLOATS * 4)

__global__ __launch_bounds__(256) void lstm_kernel(
    float* __restrict__ hseq, float* __restrict__ hlast,
    const float* __restrict__ Vf, const float* __restrict__ Vi,
    const float* __restrict__ Vo, const float* __restrict__ Vg)
{
    extern __shared__ float sm[];
    float* Vs   = sm;                // [1024*32]              32768
    float* hsm  = sm + 32768;        // [4][64*36] (pad 36)     9216
    float* gts  = sm + 41984;        // [4][32*32] partials     4096
    float* csm  = sm + 46080;        // [32*8]                   256

    const int tid   = threadIdx.x;
    const int hbase = blockIdx.x * 8;
    const int nblk  = gridDim.x;

    // Load the V slice once (persists across all 512 steps)
    {
        const float* Vp0 = Vf; const float* Vp1 = Vi;
        const float* Vp2 = Vo; const float* Vp3 = Vg;
        for (int idx = tid; idx < HID * 32; idx += 256) {
            int k = idx >> 5, c = idx & 31;
            int g = c >> 3, u = c & 7;
            const float* Vp = (g == 0) ? Vp0 : (g == 1) ? Vp1 : (g == 2) ? Vp2 : Vp3;
            Vs[idx] = Vp[(size_t)k * HID + hbase + u];
        }
    }
    for (int idx = tid; idx < 4096; idx += 256) gts[idx] = 0.f;
    if (tid < 256) csm[tid] = 0.f;
    __syncthreads();

    const int grp  = tid >> 6;            // K-group 0..3
    const int gtid = tid & 63;
    const int b0   = (gtid & 7) * 4;      // batch fragment base
    const int c0   = (gtid >> 3) * 4;     // col fragment base
    const int eu   = tid & 7;             // elementwise: unit
    const int eb   = tid >> 3;            // elementwise: batch

    for (int t = 0; t < SEQ; ++t) {
        if (t > 0) {
            float acc[16];
            #pragma unroll
            for (int i = 0; i < 16; ++i) acc[i] = 0.f;

            #pragma unroll 1
            for (int chunk = 0; chunk < 4; ++chunk) {
                const int kb = grp * 256 + chunk * 64;
                __syncthreads();
                // stage h_{t-1}[:, kb..kb+63] transposed -> hsm[grp][k][b]
                {
                    const float* hp = hseq + (size_t)(t - 1) * HID + kb + gtid;
                    float* hd = hsm + grp * 2304 + gtid * 36;
                    #pragma unroll 4
                    for (int bb = 0; bb < 32; ++bb)
                        hd[bb] = __ldcg(hp + (size_t)bb * SEQ * HID);
                }
                __syncthreads();
                const float* hrow = hsm + grp * 2304 + b0;
                const float* vrow = Vs + kb * 32 + c0;
                #pragma unroll 4
                for (int k = 0; k < 64; ++k) {
                    float4 hv = *(const float4*)(hrow + k * 36);
                    float4 vv = *(const float4*)(vrow + k * 32);
                    acc[0]  = fmaf(hv.x, vv.x, acc[0]);
                    acc[1]  = fmaf(hv.x, vv.y, acc[1]);
                    acc[2]  = fmaf(hv.x, vv.z, acc[2]);
                    acc[3]  = fmaf(hv.x, vv.w, acc[3]);
                    acc[4]  = fmaf(hv.y, vv.x, acc[4]);
                    acc[5]  = fmaf(hv.y, vv.y, acc[5]);
                    acc[6]  = fmaf(hv.y, vv.z, acc[6]);
                    acc[7]  = fmaf(hv.y, vv.w, acc[7]);
                    acc[8]  = fmaf(hv.z, vv.x, acc[8]);
                    acc[9]  = fmaf(hv.z, vv.y, acc[9]);
                    acc[10] = fmaf(hv.z, vv.z, acc[10]);
                    acc[11] = fmaf(hv.z, vv.w, acc[11]);
                    acc[12] = fmaf(hv.w, vv.x, acc[12]);
                    acc[13] = fmaf(hv.w, vv.y, acc[13]);
                    acc[14] = fmaf(hv.w, vv.z, acc[14]);
                    acc[15] = fmaf(hv.w, vv.w, acc[15]);
                }
            }
            // write partials (exclusive region per thread; prior readers synced
            // at last grid barrier)
            #pragma unroll
            for (int i = 0; i < 4; ++i) {
                float4 v = make_float4(acc[i * 4 + 0], acc[i * 4 + 1],
                                       acc[i * 4 + 2], acc[i * 4 + 3]);
                *(float4*)&gts[grp * 1024 + (b0 + i) * 32 + c0] = v;
            }
        }
        __syncthreads();

        // pointwise gate math: one thread per (batch, unit)
        {
            const size_t row  = (size_t)eb * SEQ + t;
            const float* xrow = g_xU + row * G4 + hbase + eu;
            float gs[4];
            #pragma unroll
            for (int g = 0; g < 4; ++g) {
                float s = __ldg(xrow + g * HID);
                const int gi = eb * 32 + g * 8 + eu;
                s += gts[gi] + gts[1024 + gi] + gts[2048 + gi] + gts[3072 + gi];
                gs[g] = s;
            }
            float fg = 1.f / (1.f + __expf(-gs[0]));
            float ig = 1.f / (1.f + __expf(-gs[1]));
            float og = 1.f / (1.f + __expf(-gs[2]));
            float gg = tanhf(gs[3]);
            float c  = fg * csm[eb * 8 + eu] + ig * gg;
            csm[eb * 8 + eu] = c;
            float h = og * tanhf(c);
            hseq[row * HID + hbase + eu] = h;
            if (t == SEQ - 1) hlast[(size_t)eb * HID + hbase + eu] = h;
        }

        // grid barrier (monotonic counter; reset host-side each launch)
        __threadfence();
        __syncthreads();
        if (tid == 0) {
            atomicAdd(&g_count, 1ULL);
            const unsigned long long target =
                (unsigned long long)(t + 1) * (unsigned long long)nblk;
            while (atomicAdd(&g_count, 0ULL) < target) { }
        }
        __syncthreads();
    }
}

// ------------------------------------------------------------------
extern "C" void kernel_launch(void* const* d_in, const int* in_sizes, int n_in,
                              void* d_out, int out_size)
{
    const float* x  = (const float*)d_in[0];
    const float* Uf = (const float*)d_in[1];
    const float* Vf = (const float*)d_in[2];
    const float* bf = (const float*)d_in[3];
    const float* Ui = (const float*)d_in[4];
    const float* Vi = (const float*)d_in[5];
    const float* bi = (const float*)d_in[6];
    const float* Uo = (const float*)d_in[7];
    const float* Vo = (const float*)d_in[8];
    const float* bo = (const float*)d_in[9];
    const float* Ug = (const float*)d_in[10];
    const float* Vg = (const float*)d_in[11];
    const float* bg = (const float*)d_in[12];

    float* out   = (float*)d_out;
    float* hlast = out;                    // [32][1024]
    float* hseq  = out + BSZ * HID;        // [32][512][1024]

    // reset the grid-barrier counter deterministically on every invocation
    void* cnt = nullptr;
    cudaGetSymbolAddress(&cnt, g_count);
    cudaMemsetAsync(cnt, 0, sizeof(unsigned long long), 0);

    cudaFuncSetAttribute(lstm_kernel,
                         cudaFuncAttributeMaxDynamicSharedMemorySize, SMEM_BYTES);

    dim3 ggrid(G4 / 128, (BSZ * SEQ) / 128);   // (32, 128)
    gemm_xU_kernel<<<ggrid, 256>>>(x, Uf, Ui, Uo, Ug, bf, bi, bo, bg);

    lstm_kernel<<<128, 256, SMEM_BYTES>>>(hseq, hlast, Vf, Vi, Vo, Vg);
}